// round 15
// baseline (speedup 1.0000x reference)
#include <cuda_runtime.h>

#define EPS      1e-4f
#define FRAMES   4000
#define THREADS  256
#define TILE     (THREADS * 4)        // 1024 elements per tile
#define NTILES   4                    // 4 * 1024 = 4096 >= 4000
#define NWARPS   (THREADS / 32)       // 8

__global__ __launch_bounds__(THREADS)
void cumnorm_kernel(const float* __restrict__ x, float* __restrict__ out)
{
    __shared__ float2 wsum[NTILES * NWARPS];   // [tile][warp] inclusive totals (32)

    const int tid  = threadIdx.x;
    const int lane = tid & 31;
    const int warp = tid >> 5;

    const size_t rowoff = (size_t)blockIdx.x * FRAMES;
    const float* __restrict__ xin  = x   + rowoff;
    float*       __restrict__ xout = out + rowoff;

    // ---- issue ALL loads up front (coalesced float4, MLP=4 per thread) ----
    float4 v[NTILES];
    #pragma unroll
    for (int k = 0; k < NTILES; ++k) {
        const int e = k * TILE + 4 * tid;
        if (k < NTILES - 1 || e < FRAMES)
            v[k] = *reinterpret_cast<const float4*>(xin + e);
        else
            v[k] = make_float4(0.f, 0.f, 0.f, 0.f);
    }

    // ---- per-tile thread totals straight into scan registers ----
    float is[NTILES], iq[NTILES];
    #pragma unroll
    for (int k = 0; k < NTILES; ++k) {
        const float4 vk = v[k];
        is[k] = (vk.x + vk.y) + (vk.z + vk.w);
        float q = vk.x * vk.x;
        q = fmaf(vk.y, vk.y, q);
        q = fmaf(vk.z, vk.z, q);
        iq[k] = fmaf(vk.w, vk.w, q);
    }

    // ---- 4 warp scans interleaved (8 independent shuffle chains) ----
    #pragma unroll
    for (int d = 1; d < 32; d <<= 1) {
        #pragma unroll
        for (int k = 0; k < NTILES; ++k) {
            float as = __shfl_up_sync(0xffffffffu, is[k], d);
            float aq = __shfl_up_sync(0xffffffffu, iq[k], d);
            if (lane >= d) { is[k] += as; iq[k] += aq; }
        }
    }

    if (lane == 31) {
        #pragma unroll
        for (int k = 0; k < NTILES; ++k)
            wsum[k * NWARPS + warp] = make_float2(is[k], iq[k]);
    }

    // ---- per-thread EXCLUSIVE prefix via one more shfl (lets totals die) ----
    float es[NTILES], eq[NTILES];
    #pragma unroll
    for (int k = 0; k < NTILES; ++k) {
        float as = __shfl_up_sync(0xffffffffu, is[k], 1);
        float aq = __shfl_up_sync(0xffffffffu, iq[k], 1);
        es[k] = (lane > 0) ? as : 0.f;
        eq[k] = (lane > 0) ? aq : 0.f;
    }
    __syncthreads();     // the ONLY barrier

    // ---- every warp redundantly scans all 32 [tile][warp] totals (full scan):
    //      lane (k*8 + w) then holds the GLOBAL inclusive prefix through
    //      tile k, warp w — inter-tile carry comes for free.
    float ws, wq;
    {
        const float2 w0 = wsum[lane];
        ws = w0.x; wq = w0.y;
        #pragma unroll
        for (int d = 1; d < 32; d <<= 1) {
            float as = __shfl_up_sync(0xffffffffu, ws, d);
            float aq = __shfl_up_sync(0xffffffffu, wq, d);
            if (lane >= d) { ws += as; wq += aq; }
        }
    }

    // ---- tail: normalize + store; global prefix via shfl broadcast ----
    #pragma unroll
    for (int k = 0; k < NTILES; ++k) {
        const int src = k * NWARPS + warp - 1;        // uniform per warp
        float gs = __shfl_sync(0xffffffffu, ws, src & 31);
        float gq = __shfl_sync(0xffffffffu, wq, src & 31);
        if (src < 0) { gs = 0.f; gq = 0.f; }          // only k==0 && warp==0

        float ps = gs + es[k];
        float pq = gq + eq[k];

        const int e = k * TILE + 4 * tid;
        if (k < NTILES - 1 || e < FRAMES) {
            float r[4] = {v[k].x, v[k].y, v[k].z, v[k].w};
            float c = (float)e;
            #pragma unroll
            for (int j = 0; j < 4; ++j) {
                const float xv = r[j];
                ps += xv;
                pq  = fmaf(xv, xv, pq);
                c  += 1.f;
                const float ecc = (EPS * c) * c;
                const float den = fmaf(c, pq, fmaf(-ps, ps, ecc)); // c*q - s^2 + eps*c^2
                const float num = fmaf(c, xv, -ps);                // c*x - s
                r[j] = num * rsqrtf(den);
            }
            *reinterpret_cast<float4*>(xout + e) =
                make_float4(r[0], r[1], r[2], r[3]);
        }
    }
}

extern "C" void kernel_launch(void* const* d_in, const int* in_sizes, int n_in,
                              void* d_out, int out_size)
{
    const float* x = (const float*)d_in[0];
    float* outp    = (float*)d_out;
    const int rows = in_sizes[0] / FRAMES;   // 32 * 512 = 16384
    cumnorm_kernel<<<rows, THREADS>>>(x, outp);
}

// round 16
// speedup vs baseline: 1.4216x; 1.4216x over previous
#include <cuda_runtime.h>

#define EPS      1e-4f
#define FRAMES   4000
#define THREADS  256
#define TILE     (THREADS * 4)        // 1024 elements per tile
#define NTILES   4                    // 4 * 1024 = 4096 >= 4000
#define NWARPS   (THREADS / 32)       // 8

__global__ __launch_bounds__(THREADS)
void cumnorm_kernel(const float* __restrict__ x, float* __restrict__ out)
{
    __shared__ float2 wsum[NTILES * NWARPS];   // [tile][warp] totals -> global prefixes
    __shared__ char   occ_pad[40960];          // pin 5 blocks/SM (228KB/40KB = 5)

    const int tid  = threadIdx.x;
    const int lane = tid & 31;
    const int warp = tid >> 5;

    // keep the pad alive without doing work (compiler can't prove false at compile time)
    if (blockIdx.x > 0x0FFFFFFF) occ_pad[tid] = 1;

    const size_t rowoff = (size_t)blockIdx.x * FRAMES;
    const float* __restrict__ xin  = x   + rowoff;
    float*       __restrict__ xout = out + rowoff;

    // ---- issue ALL loads up front (coalesced float4, MLP=4 per thread) ----
    float4 v[NTILES];
    #pragma unroll
    for (int k = 0; k < NTILES; ++k) {
        const int e = k * TILE + 4 * tid;
        if (k < NTILES - 1 || e < FRAMES)
            v[k] = *reinterpret_cast<const float4*>(xin + e);
        else
            v[k] = make_float4(0.f, 0.f, 0.f, 0.f);
    }

    // ---- per-tile thread totals straight into scan registers ----
    float is[NTILES], iq[NTILES];
    #pragma unroll
    for (int k = 0; k < NTILES; ++k) {
        const float4 vk = v[k];
        is[k] = (vk.x + vk.y) + (vk.z + vk.w);
        float q = vk.x * vk.x;
        q = fmaf(vk.y, vk.y, q);
        q = fmaf(vk.z, vk.z, q);
        iq[k] = fmaf(vk.w, vk.w, q);
    }

    // ---- 4 warp scans interleaved (8 independent shuffle chains) ----
    #pragma unroll
    for (int d = 1; d < 32; d <<= 1) {
        #pragma unroll
        for (int k = 0; k < NTILES; ++k) {
            float as = __shfl_up_sync(0xffffffffu, is[k], d);
            float aq = __shfl_up_sync(0xffffffffu, iq[k], d);
            if (lane >= d) { is[k] += as; iq[k] += aq; }
        }
    }

    if (lane == 31) {
        #pragma unroll
        for (int k = 0; k < NTILES; ++k)
            wsum[k * NWARPS + warp] = make_float2(is[k], iq[k]);
    }

    // ---- per-thread EXCLUSIVE prefix via one more shfl (lets totals die) ----
    float es[NTILES], eq[NTILES];
    #pragma unroll
    for (int k = 0; k < NTILES; ++k) {
        float as = __shfl_up_sync(0xffffffffu, is[k], 1);
        float aq = __shfl_up_sync(0xffffffffu, iq[k], 1);
        es[k] = (lane > 0) ? as : 0.f;
        eq[k] = (lane > 0) ? aq : 0.f;
    }
    __syncthreads();

    // ---- warp 0: ONE FULL scan over all 32 [tile][warp] totals.
    //      Afterward wsum[i] = GLOBAL inclusive prefix through entry i,
    //      so wsum[k*8 + warp - 1] is the global exclusive prefix for
    //      (tile k, warp) — inter-tile carry included for free.
    if (warp == 0) {
        float2 w = wsum[lane];
        float ws = w.x, wq = w.y;
        #pragma unroll
        for (int d = 1; d < 32; d <<= 1) {
            float as = __shfl_up_sync(0xffffffffu, ws, d);
            float aq = __shfl_up_sync(0xffffffffu, wq, d);
            if (lane >= d) { ws += as; wq += aq; }
        }
        wsum[lane] = make_float2(ws, wq);
    }
    __syncthreads();

    // ---- tail: 4 independent normalize+store loops (no carry chain) ----
    #pragma unroll
    for (int k = 0; k < NTILES; ++k) {
        const int   idx = k * NWARPS + warp - 1;
        const float2 g  = (idx >= 0) ? wsum[idx] : make_float2(0.f, 0.f);
        float ps = g.x + es[k];
        float pq = g.y + eq[k];

        const int e = k * TILE + 4 * tid;
        if (k < NTILES - 1 || e < FRAMES) {
            float r[4] = {v[k].x, v[k].y, v[k].z, v[k].w};
            float c = (float)e;
            #pragma unroll
            for (int j = 0; j < 4; ++j) {
                const float xv = r[j];
                ps += xv;
                pq  = fmaf(xv, xv, pq);
                c  += 1.f;
                // den = c*pq + EPS*c^2 - ps^2  (strength-reduced form)
                const float t   = fmaf(EPS, c, pq);
                const float m   = ps * ps;
                const float den = fmaf(c, t, -m);
                const float num = fmaf(c, xv, -ps);     // c*x - s
                r[j] = num * rsqrtf(den);
            }
            *reinterpret_cast<float4*>(xout + e) =
                make_float4(r[0], r[1], r[2], r[3]);
        }
    }
}

extern "C" void kernel_launch(void* const* d_in, const int* in_sizes, int n_in,
                              void* d_out, int out_size)
{
    const float* x = (const float*)d_in[0];
    float* outp    = (float*)d_out;
    const int rows = in_sizes[0] / FRAMES;   // 32 * 512 = 16384
    cumnorm_kernel<<<rows, THREADS>>>(x, outp);
}